// round 12
// baseline (speedup 1.0000x reference)
#include <cuda_runtime.h>
#include <math.h>

#define NMAX  12288
#define SEG   1536            // NMAX / NSEG
#define NSEG  8
#define QB    128             // threads per block
#define NB    768             // persistent blocks: 6/SM x 148 = 888 >= 768, co-resident
#define EPT   (SEG / QB)      // 12 elements/thread in segment scan
#define SBLK  (NMAX / QB)     // 96 strain blocks
#define QW    256             // queries per window (2 per thread)
#define CAPC  512             // candidates per tile chunk (packed, 16KB)

struct CMat { float m[9]; float s; };

// ---- persistent scratch (zero-init at load; monotone counters, no resets) ----
__device__ float4 g_cand[NMAX];                 // compacted {x,y,z,|w|^2}; padded BIG
__device__ int    g_cidx[NMAX];                 // compact slot -> original index
__device__ int    g_cnt[NSEG];
__device__ unsigned long long g_best[NMAX];     // ~((ord(d)<<32)|slot); 0 = armed
__device__ double g_bsum[SBLK];
__device__ int    g_bcnt[SBLK];
__device__ unsigned int g_c1, g_c2, g_c3;       // monotone barrier/ticket counters

__device__ __forceinline__ unsigned int ford(float f) {
    unsigned int u = __float_as_uint(f);
    return (u & 0x80000000u) ? ~u : (u | 0x80000000u);
}
__device__ __forceinline__ float finv(unsigned int o) {
    unsigned int u = (o & 0x80000000u) ? (o ^ 0x80000000u) : ~o;
    return __uint_as_float(u);
}

// ---- packed fp32x2 helpers (sm_103a) ----
__device__ __forceinline__ unsigned long long fma2(unsigned long long a,
                                                   unsigned long long b,
                                                   unsigned long long c) {
    unsigned long long d;
    asm("fma.rn.f32x2 %0, %1, %2, %3;" : "=l"(d) : "l"(a), "l"(b), "l"(c));
    return d;
}
__device__ __forceinline__ unsigned long long pack2(float lo, float hi) {
    unsigned long long r;
    asm("mov.b64 %0, {%1, %2};" : "=l"(r) : "f"(lo), "f"(hi));
    return r;
}
__device__ __forceinline__ void unpack2(float& lo, float& hi, unsigned long long v) {
    asm("mov.b64 {%0, %1}, %2;" : "=f"(lo), "=f"(hi) : "l"(v));
}

// monotone grid barrier (no reset -> no stale-spinner hazard across replays)
__device__ __forceinline__ void gbar(unsigned int* ctr) {
    __syncthreads();
    if (threadIdx.x == 0) {
        __threadfence();
        unsigned int v = atomicAdd(ctr, 1u);
        unsigned int target = (v / NB + 1u) * NB;
        while (*(volatile unsigned int*)ctr < target) __nanosleep(32);
        __threadfence();
    }
    __syncthreads();
}

// ============================================================
// One persistent kernel: compact -> gbar -> NN (2q/thread, f32x2 packed FMA)
// -> gbar -> strain+reduce
// ============================================================
__global__ void __launch_bounds__(QB, 6) k_all(const float* __restrict__ new_xyz,
                                               const float* __restrict__ xyz,
                                               const float* __restrict__ gt_sdf,
                                               CMat C, float* __restrict__ out) {
    // packed tile: per candidate 2x ulonglong2 = {x,x}{y,y} and {z,z}{w,w}
    __shared__ ulonglong2 tile[2 * (CAPC + 4)];   // 16.5 KB
    __shared__ int    s_w[4];
    __shared__ int    s_pw[NSEG + 1];
    __shared__ int    s_cnt[NSEG];
    __shared__ double s_rd[QB];
    __shared__ int    s_ri[QB];
    __shared__ int    s_last;

    int tid = threadIdx.x, lane = tid & 31, wid = tid >> 5;
    int b   = blockIdx.x;

    // ---------------- Phase 0: compaction (blocks 0..7) ----------------
    if (b < NSEG) {
        int s0 = b * SEG;
        const float4* ps = (const float4*)(gt_sdf + s0 + EPT * tid);
        float4 a = ps[0], bb = ps[1], cc = ps[2];
        float v[12] = {a.x,a.y,a.z,a.w, bb.x,bb.y,bb.z,bb.w, cc.x,cc.y,cc.z,cc.w};
        unsigned fl = 0; int myc = 0;
        #pragma unroll
        for (int e = 0; e < 12; ++e) if (v[e] < 1e-8f) { fl |= 1u << e; myc++; }
        int pre = myc;
        #pragma unroll
        for (int o = 1; o < 32; o <<= 1) { int t2 = __shfl_up_sync(~0u, pre, o); if (lane >= o) pre += t2; }
        if (lane == 31) s_w[wid] = pre;
        __syncthreads();
        int woff = 0;
        #pragma unroll
        for (int w = 0; w < 4; ++w) if (w < wid) woff += s_w[w];
        int pos = woff + pre - myc;
        int cnt = s_w[0] + s_w[1] + s_w[2] + s_w[3];
        #pragma unroll
        for (int e = 0; e < 12; ++e) {
            if (fl & (1u << e)) {
                int idx = s0 + EPT * tid + e;
                float x = new_xyz[3 * idx + 0];
                float y = new_xyz[3 * idx + 1];
                float z = new_xyz[3 * idx + 2];
                g_cand[s0 + pos] = make_float4(x, y, z, x * x + y * y + z * z);
                g_cidx[s0 + pos] = idx;
                pos++;
            }
        }
        for (int p = cnt + tid; p < SEG; p += QB)
            g_cand[s0 + p] = make_float4(0.f, 0.f, 0.f, 1e30f);
        if (tid == 0) g_cnt[b] = cnt;
    }

    gbar(&g_c1);

    // ---------------- Phase 1: NN, one uniform item per block ----------------
    if (tid < NSEG) s_cnt[tid] = g_cnt[tid];
    __syncthreads();
    if (tid == 0) {
        int acc = 0;
        #pragma unroll
        for (int s = 0; s < NSEG; ++s) {
            s_pw[s] = acc;
            acc += (s_cnt[s] + QW - 1) / QW;              // 256-query windows
        }
        s_pw[NSEG] = acc;
    }
    __syncthreads();
    {
        int w8   = s_pw[NSEG] * NSEG;                     // (window, cand-seg) pairs
        int S    = NB / w8;                               // slices per pair (>=1)
        int used = w8 * S;

        if (b < used) {
            int wi    = b % w8;
            int slice = b / w8;
            int widx  = wi >> 3;
            int cs    = wi & 7;
            int qseg  = 0;
            #pragma unroll
            for (int s = 0; s < NSEG - 1; ++s) if (widx >= s_pw[s + 1]) qseg = s + 1;
            int qw0  = (widx - s_pw[qseg]) * QW;
            int cntq = s_cnt[qseg];

            int cntseg = s_cnt[cs];
            int lo   = (int)((long long)slice * cntseg / S);
            int hi   = (int)((long long)(slice + 1) * cntseg / S);

            // queries (2 per thread)
            int ql0 = qw0 + tid, ql1 = qw0 + QB + tid;
            bool qa0 = (ql0 < cntq), qa1 = (ql1 < cntq);
            float4 w0 = g_cand[qseg * SEG + min(ql0, SEG - 1)];
            float4 w1 = g_cand[qseg * SEG + min(ql1, SEG - 1)];
            float ax0 = -2.f * w0.x, ay0 = -2.f * w0.y, az0 = -2.f * w0.z;
            float ax1 = -2.f * w1.x, ay1 = -2.f * w1.y, az1 = -2.f * w1.z;
            unsigned long long ax2 = pack2(ax0, ax1);
            unsigned long long ay2 = pack2(ay0, ay1);
            unsigned long long az2 = pack2(az0, az1);

            unsigned long long bkey0 = 0xffffffffffffffffULL;
            unsigned long long bkey1 = 0xffffffffffffffffULL;

            // chunk loop over the slice (expected 1 iteration)
            for (int c0 = lo; c0 < hi; c0 += CAPC) {
                int cc = min(CAPC, hi - c0);
                if (c0 != lo) __syncthreads();            // tile reuse
                for (int k = tid; k < cc; k += QB) {      // build packed tile
                    float4 c = g_cand[cs * SEG + c0 + k];
                    tile[2 * k]     = make_ulonglong2(pack2(c.x, c.x), pack2(c.y, c.y));
                    tile[2 * k + 1] = make_ulonglong2(pack2(c.z, c.z), pack2(c.w, c.w));
                }
                if (tid < 4) {                            // pad for batch-4
                    tile[2 * (cc + tid)]     = make_ulonglong2(pack2(0.f, 0.f), pack2(0.f, 0.f));
                    tile[2 * (cc + tid) + 1] = make_ulonglong2(pack2(0.f, 0.f), pack2(1e30f, 1e30f));
                }
                __syncthreads();

                int sk0 = ql0 - c0, sk1 = ql1 - c0;       // self slots within chunk
                bool overlap = (cs == qseg) && (c0 < qw0 + QW) && (c0 + cc > qw0);
                int cc4 = (cc + 3) & ~3;
                float best0 = 3.0e38f, best1 = 3.0e38f;
                int   kb0 = 0, kb1 = 0;

                if (!overlap) {
                    for (int k = 0; k < cc4; k += 4) {
                        ulonglong2 p00 = tile[2*k+0], p01 = tile[2*k+1];
                        ulonglong2 p10 = tile[2*k+2], p11 = tile[2*k+3];
                        ulonglong2 p20 = tile[2*k+4], p21 = tile[2*k+5];
                        ulonglong2 p30 = tile[2*k+6], p31 = tile[2*k+7];
                        unsigned long long d2_0 = fma2(p00.x, ax2, fma2(p00.y, ay2, fma2(p01.x, az2, p01.y)));
                        unsigned long long d2_1 = fma2(p10.x, ax2, fma2(p10.y, ay2, fma2(p11.x, az2, p11.y)));
                        unsigned long long d2_2 = fma2(p20.x, ax2, fma2(p20.y, ay2, fma2(p21.x, az2, p21.y)));
                        unsigned long long d2_3 = fma2(p30.x, ax2, fma2(p30.y, ay2, fma2(p31.x, az2, p31.y)));
                        float dA0, dB0, dA1, dB1, dA2, dB2, dA3, dB3;
                        unpack2(dA0, dB0, d2_0);
                        unpack2(dA1, dB1, d2_1);
                        unpack2(dA2, dB2, d2_2);
                        unpack2(dA3, dB3, d2_3);
                        float mA = fminf(fminf(dA0, dA1), fminf(dA2, dA3));
                        float mB = fminf(fminf(dB0, dB1), fminf(dB2, dB3));
                        if (mA < best0) { best0 = mA; kb0 = k; }
                        if (mB < best1) { best1 = mB; kb1 = k; }
                    }
                } else {
                    for (int k = 0; k < cc4; k += 4) {
                        ulonglong2 p00 = tile[2*k+0], p01 = tile[2*k+1];
                        ulonglong2 p10 = tile[2*k+2], p11 = tile[2*k+3];
                        ulonglong2 p20 = tile[2*k+4], p21 = tile[2*k+5];
                        ulonglong2 p30 = tile[2*k+6], p31 = tile[2*k+7];
                        unsigned long long d2_0 = fma2(p00.x, ax2, fma2(p00.y, ay2, fma2(p01.x, az2, p01.y)));
                        unsigned long long d2_1 = fma2(p10.x, ax2, fma2(p10.y, ay2, fma2(p11.x, az2, p11.y)));
                        unsigned long long d2_2 = fma2(p20.x, ax2, fma2(p20.y, ay2, fma2(p21.x, az2, p21.y)));
                        unsigned long long d2_3 = fma2(p30.x, ax2, fma2(p30.y, ay2, fma2(p31.x, az2, p31.y)));
                        float dA0, dB0, dA1, dB1, dA2, dB2, dA3, dB3;
                        unpack2(dA0, dB0, d2_0);
                        unpack2(dA1, dB1, d2_1);
                        unpack2(dA2, dB2, d2_2);
                        unpack2(dA3, dB3, d2_3);
                        if (__any_sync(0xffffffffu, ((unsigned)(sk0 - k) < 4u) |
                                                    ((unsigned)(sk1 - k) < 4u))) {  // rare
                            dA0 = (k + 0 == sk0) ? 3e38f : dA0;
                            dA1 = (k + 1 == sk0) ? 3e38f : dA1;
                            dA2 = (k + 2 == sk0) ? 3e38f : dA2;
                            dA3 = (k + 3 == sk0) ? 3e38f : dA3;
                            dB0 = (k + 0 == sk1) ? 3e38f : dB0;
                            dB1 = (k + 1 == sk1) ? 3e38f : dB1;
                            dB2 = (k + 2 == sk1) ? 3e38f : dB2;
                            dB3 = (k + 3 == sk1) ? 3e38f : dB3;
                        }
                        float mA = fminf(fminf(dA0, dA1), fminf(dA2, dA3));
                        float mB = fminf(fminf(dB0, dB1), fminf(dB2, dB3));
                        if (mA < best0) { best0 = mA; kb0 = k; }
                        if (mB < best1) { best1 = mB; kb1 = k; }
                    }
                }

                // recovery: first element of winning batch with d == best
                // (scalar fmaf, same nesting order -> bit-identical to f32x2 halves)
                const float* tf = (const float*)tile;     // [x,x,y,y,z,z,w,w] per cand
                if (qa0) {
                    int bi = kb0; bool found = false;
                    #pragma unroll
                    for (int i2 = 0; i2 < 4; ++i2) {
                        int e = kb0 + i2;
                        float d = fmaf(tf[8*e], ax0, fmaf(tf[8*e+2], ay0, fmaf(tf[8*e+4], az0, tf[8*e+6])));
                        bool self = overlap && (e == sk0);
                        if (!found && !self && d == best0) { bi = e; found = true; }
                    }
                    unsigned long long key =
                        ((unsigned long long)ford(best0) << 32) | (unsigned int)(cs * SEG + c0 + bi);
                    if (key < bkey0) bkey0 = key;
                }
                if (qa1) {
                    int bi = kb1; bool found = false;
                    #pragma unroll
                    for (int i2 = 0; i2 < 4; ++i2) {
                        int e = kb1 + i2;
                        float d = fmaf(tf[8*e], ax1, fmaf(tf[8*e+2], ay1, fmaf(tf[8*e+4], az1, tf[8*e+6])));
                        bool self = overlap && (e == sk1);
                        if (!found && !self && d == best1) { bi = e; found = true; }
                    }
                    unsigned long long key =
                        ((unsigned long long)ford(best1) << 32) | (unsigned int)(cs * SEG + c0 + bi);
                    if (key < bkey1) bkey1 = key;
                }
            }

            if (qa0 && bkey0 != 0xffffffffffffffffULL)
                atomicMax(&g_best[qseg * SEG + ql0], ~bkey0);   // max(~key) == min(key)
            if (qa1 && bkey1 != 0xffffffffffffffffULL)
                atomicMax(&g_best[qseg * SEG + ql1], ~bkey1);
        }
    }

    gbar(&g_c2);

    // ---------------- Phase 2: strain + reduction (blocks 0..95) ----------
    if (b >= SBLK) return;

    int slot = b * QB + tid;                              // compact query slot
    int qseg2 = slot / SEG;
    int ql2   = slot - qseg2 * SEG;
    double qsq = 0.0;
    int cnt = 0;
    unsigned long long kp = g_best[slot];
    g_best[slot] = 0ULL;                                  // re-arm for next replay
    if (kp != 0ULL && ql2 < g_cnt[qseg2]) {
        unsigned long long key = ~kp;
        float deff = finv((unsigned int)(key >> 32));
        int   nslot = (int)(unsigned int)(key & 0xffffffffu);
        int   i  = g_cidx[slot];
        int   nn = g_cidx[nslot];
        float wqx = new_xyz[3 * i + 0], wqy = new_xyz[3 * i + 1], wqz = new_xyz[3 * i + 2];
        float sqi = wqx * wqx + wqy * wqy + wqz * wqz;
        float mind2 = deff + sqi;                         // add back sq_i
        if (mind2 > 1e-16f) {                             // inside & (nn_d > 1e-8)
            cnt = 1;
            float wnx = new_xyz[3 * nn + 0], wny = new_xyz[3 * nn + 1], wnz = new_xyz[3 * nn + 2];
            float xi0 = xyz[3 * i + 0],  xi1 = xyz[3 * i + 1],  xi2 = xyz[3 * i + 2];
            float xn0 = xyz[3 * nn + 0], xn1 = xyz[3 * nn + 1], xn2 = xyz[3 * nn + 2];
            float du = (wnx - xn0) - (wqx - xi0);         // dm = motion[nn] - motion[i]
            float dv = (wny - xn1) - (wqy - xi1);
            float dw = (wnz - xn2) - (wqz - xi2);
            float dx = wnx - wqx + 1e-8f;
            float dy = wny - wqy + 1e-8f;
            float dz = wnz - wqz + 1e-8f;
            float e0 = du / dx, e1 = dv / dy, e2 = dw / dz;
            float e3 = (du / dy + dv / dx) * 0.5f;
            float e4 = (du / dz + dw / dx) * 0.5f;
            float e5 = (dw / dy + dv / dz) * 0.5f;
            float r0 = C.m[0] * e0 + C.m[1] * e1 + C.m[2] * e2;
            float r1 = C.m[3] * e0 + C.m[4] * e1 + C.m[5] * e2;
            float r2 = C.m[6] * e0 + C.m[7] * e1 + C.m[8] * e2;
            float q  = e0 * r0 + e1 * r1 + e2 * r2
                     + C.s * (e3 * e3 + e4 * e4 + e5 * e5);
            qsq = (double)q * (double)q;
        }
    }
    s_rd[tid] = qsq;
    s_ri[tid] = cnt;
    __syncthreads();
    #pragma unroll
    for (int o = QB / 2; o > 0; o >>= 1) {                // deterministic tree
        if (tid < o) { s_rd[tid] += s_rd[tid + o]; s_ri[tid] += s_ri[tid + o]; }
        __syncthreads();
    }
    if (tid == 0) {
        g_bsum[b] = s_rd[0];
        g_bcnt[b] = s_ri[0];
        __threadfence();
        unsigned int v = atomicAdd(&g_c3, 1u);
        s_last = ((v % SBLK) == SBLK - 1);                // monotone ticket
    }
    __syncthreads();

    if (s_last) {
        __threadfence();
        double s = 0.0; int c = 0;
        if (tid < SBLK) { s = g_bsum[tid]; c = g_bcnt[tid]; }
        s_rd[tid] = s; s_ri[tid] = c;
        __syncthreads();
        #pragma unroll
        for (int o = QB / 2; o > 0; o >>= 1) {
            if (tid < o) { s_rd[tid] += s_rd[tid + o]; s_ri[tid] += s_ri[tid + o]; }
            __syncthreads();
        }
        if (tid == 0)
            out[0] = (float)(sqrt(s_rd[0]) / (double)s_ri[0]);
    }
}

// ============================================================
extern "C" void kernel_launch(void* const* d_in, const int* in_sizes, int n_in,
                              void* d_out, int out_size) {
    const float* new_xyz = (const float*)d_in[0];
    const float* xyz     = (const float*)d_in[1];
    const float* gt_sdf  = (const float*)d_in[2];

    CMat C;
    {
        const double EP = 0.21, VP = 0.4;
        double A[3][3] = {{1.0/EP, -VP/EP, -VP/EP},
                          {-VP/EP, 1.0/EP, -VP/EP},
                          {-VP,    -VP,    1.0/EP}};
        double det = A[0][0]*(A[1][1]*A[2][2]-A[1][2]*A[2][1])
                   - A[0][1]*(A[1][0]*A[2][2]-A[1][2]*A[2][0])
                   + A[0][2]*(A[1][0]*A[2][1]-A[1][1]*A[2][0]);
        double inv[3][3];
        inv[0][0] = (A[1][1]*A[2][2]-A[1][2]*A[2][1])/det;
        inv[0][1] = (A[0][2]*A[2][1]-A[0][1]*A[2][2])/det;
        inv[0][2] = (A[0][1]*A[1][2]-A[0][2]*A[1][1])/det;
        inv[1][0] = (A[1][2]*A[2][0]-A[1][0]*A[2][2])/det;
        inv[1][1] = (A[0][0]*A[2][2]-A[0][2]*A[2][0])/det;
        inv[1][2] = (A[0][2]*A[1][0]-A[0][0]*A[1][2])/det;
        inv[2][0] = (A[1][0]*A[2][1]-A[1][1]*A[2][0])/det;
        inv[2][1] = (A[0][1]*A[2][0]-A[0][0]*A[2][1])/det;
        inv[2][2] = (A[0][0]*A[1][1]-A[0][1]*A[1][0])/det;
        for (int i = 0; i < 3; i++)
            for (int j = 0; j < 3; j++)
                C.m[i * 3 + j] = (float)inv[i][j];
        C.s = (float)(EP / (2.0 * (1.0 + VP)));
    }

    k_all<<<NB, QB>>>(new_xyz, xyz, gt_sdf, C, (float*)d_out);
}